// round 15
// baseline (speedup 1.0000x reference)
#include <cuda_runtime.h>
#include <cuda_fp16.h>
#include <cstdint>

#define T_TOK 8192
#define DIM   1024
#define HID   4096
#define NEXP  8
#define BM 128
#define BN 128
#define BK 64                      // k elements per stage (fp16)
#define NMPAD  136
#define MAXPAD (NMPAD * BM)

#define SAH 72                     // smem row stride in halves (144 bytes)
#define ATILEH (BM * SAH)          // 9216 halves per tile
#define STGB (2 * ATILEH * 2)      // 36864 bytes per stage (A+B)
#define NSTG 3
#define SMEM_DYN (NSTG * STGB)     // 110592 bytes -> 2 CTAs/SM

// ---------------- scratch ----------------
__device__ __half g_gh[(size_t)MAXPAD * HID];      // raw gate g in fp16
__device__ __half g_hh[(size_t)MAXPAD * HID];      // h = silu(g)*u in fp16
__device__ __half g_xh[(size_t)T_TOK * DIM];       // x in fp16
__device__ __half g_wgT[(size_t)NEXP * HID * DIM]; // w_gate^T [e][n][k] fp16
__device__ __half g_wuT[(size_t)NEXP * HID * DIM];
__device__ __half g_wdT[(size_t)NEXP * DIM * HID];
__device__ int    g_perm[MAXPAD];
__device__ float  g_permw[MAXPAD];
__device__ int    g_offpad[NEXP + 1];
__device__ int    g_cnt[NEXP];
__device__ int    g_cursor[NEXP];
__device__ float  g_probsum[NEXP];
__device__ int    g_topi[T_TOK * 2];
__device__ float  g_topw[T_TOK * 2];

// ---------------- helpers ----------------
__device__ __forceinline__ uint32_t smem_u32(const void* p) {
    uint32_t a;
    asm("{ .reg .u64 t; cvta.to.shared.u64 t, %1; cvt.u32.u64 %0, t; }"
        : "=r"(a) : "l"(p));
    return a;
}
__device__ __forceinline__ void cp16h(uint32_t d, const __half* s, uint32_t sz) {
    asm volatile("cp.async.cg.shared.global [%0], [%1], 16, %2;"
                 :: "r"(d), "l"(s), "r"(sz));
}
#define CP_COMMIT() asm volatile("cp.async.commit_group;" ::: "memory")
#define CP_WAIT1()  asm volatile("cp.async.wait_group 1;" ::: "memory")

__device__ __forceinline__ void mma_f16(float* c, const uint32_t* a,
                                        const uint32_t* b) {
    asm volatile(
        "mma.sync.aligned.m16n8k16.row.col.f32.f16.f16.f32 "
        "{%0,%1,%2,%3}, {%4,%5,%6,%7}, {%8,%9}, {%0,%1,%2,%3};"
        : "+f"(c[0]), "+f"(c[1]), "+f"(c[2]), "+f"(c[3])
        : "r"(a[0]), "r"(a[1]), "r"(a[2]), "r"(a[3]), "r"(b[0]), "r"(b[1]));
}

__device__ __forceinline__ void ldsm_x4(uint32_t* r, uint32_t addr) {
    asm volatile("ldmatrix.sync.aligned.m8n8.x4.shared.b16 {%0,%1,%2,%3}, [%4];"
                 : "=r"(r[0]), "=r"(r[1]), "=r"(r[2]), "=r"(r[3]) : "r"(addr));
}

// ---------------- small kernels ----------------
__global__ void k_init0() {
    int i = threadIdx.x;
    if (i < NEXP) { g_cnt[i] = 0; g_cursor[i] = 0; g_probsum[i] = 0.f; }
}

__global__ void k_zero_out(float4* out, int n4) {
    float4 z = make_float4(0.f, 0.f, 0.f, 0.f);
    for (int i = blockIdx.x * blockDim.x + threadIdx.x; i < n4;
         i += gridDim.x * blockDim.x)
        out[i] = z;
}

// transpose+convert: src fp32 [e][R][C] -> dst fp16 [e][C][R], 64x64 tiles
__global__ void k_tr(const float* __restrict__ src, int R, int C, int sel) {
    __half* dstb = (sel == 0) ? g_wgT : (sel == 1) ? g_wuT : g_wdT;
    __shared__ float t[64][65];
    size_t mo = (size_t)blockIdx.z * R * C;
    const float* s = src + mo;
    __half* d = dstb + mo;
    int c0 = blockIdx.x * 64, r0 = blockIdx.y * 64;
    int tx = threadIdx.x, ty = threadIdx.y;
#pragma unroll
    for (int j = ty; j < 64; j += 8) {
        float2 v = *(const float2*)&s[(size_t)(r0 + j) * C + c0 + tx * 2];
        t[j][tx * 2] = v.x; t[j][tx * 2 + 1] = v.y;
    }
    __syncthreads();
#pragma unroll
    for (int j = ty; j < 64; j += 8) {
        __half2 h = __floats2half2_rn(t[tx * 2][j], t[tx * 2 + 1][j]);
        *(__half2*)&d[(size_t)(c0 + j) * R + r0 + tx * 2] = h;
    }
}

// gating + fused x->fp16 conversion, float4-vectorized
__global__ void k_gate(const float* __restrict__ x, const float* __restrict__ gw) {
    int gwarp = (blockIdx.x * blockDim.x + threadIdx.x) >> 5;
    int lane  = threadIdx.x & 31;
    if (gwarp >= T_TOK) return;
    const float4* xr = (const float4*)(x + (size_t)gwarp * DIM);
    __half2* xh = (__half2*)(g_xh + (size_t)gwarp * DIM);

    float acc[NEXP];
#pragma unroll
    for (int e = 0; e < NEXP; e++) acc[e] = 0.f;
    for (int i = lane; i < DIM / 4; i += 32) {
        float4 xv = xr[i];
        xh[2 * i]     = __floats2half2_rn(xv.x, xv.y);
        xh[2 * i + 1] = __floats2half2_rn(xv.z, xv.w);
        const float4* g = (const float4*)(gw + (size_t)i * 4 * NEXP);
        float4 r0a = g[0], r0b = g[1], r1a = g[2], r1b = g[3];
        float4 r2a = g[4], r2b = g[5], r3a = g[6], r3b = g[7];
        acc[0] += xv.x * r0a.x; acc[1] += xv.x * r0a.y;
        acc[2] += xv.x * r0a.z; acc[3] += xv.x * r0a.w;
        acc[4] += xv.x * r0b.x; acc[5] += xv.x * r0b.y;
        acc[6] += xv.x * r0b.z; acc[7] += xv.x * r0b.w;
        acc[0] += xv.y * r1a.x; acc[1] += xv.y * r1a.y;
        acc[2] += xv.y * r1a.z; acc[3] += xv.y * r1a.w;
        acc[4] += xv.y * r1b.x; acc[5] += xv.y * r1b.y;
        acc[6] += xv.y * r1b.z; acc[7] += xv.y * r1b.w;
        acc[0] += xv.z * r2a.x; acc[1] += xv.z * r2a.y;
        acc[2] += xv.z * r2a.z; acc[3] += xv.z * r2a.w;
        acc[4] += xv.z * r2b.x; acc[5] += xv.z * r2b.y;
        acc[6] += xv.z * r2b.z; acc[7] += xv.z * r2b.w;
        acc[0] += xv.w * r3a.x; acc[1] += xv.w * r3a.y;
        acc[2] += xv.w * r3a.z; acc[3] += xv.w * r3a.w;
        acc[4] += xv.w * r3b.x; acc[5] += xv.w * r3b.y;
        acc[6] += xv.w * r3b.z; acc[7] += xv.w * r3b.w;
    }
#pragma unroll
    for (int off = 16; off > 0; off >>= 1)
#pragma unroll
        for (int e = 0; e < NEXP; e++)
            acc[e] += __shfl_xor_sync(0xffffffffu, acc[e], off);

    float mx = acc[0];
#pragma unroll
    for (int e = 1; e < NEXP; e++) mx = fmaxf(mx, acc[e]);
    float p[NEXP], s = 0.f;
#pragma unroll
    for (int e = 0; e < NEXP; e++) { p[e] = __expf(acc[e] - mx); s += p[e]; }
    float inv = 1.f / s;
    if (lane < NEXP) atomicAdd(&g_probsum[lane], p[lane] * inv);

    if (lane == 0) {
        int i0 = 0;
#pragma unroll
        for (int e = 1; e < NEXP; e++) if (acc[e] > acc[i0]) i0 = e;
        int i1 = (i0 == 0) ? 1 : 0;
#pragma unroll
        for (int e = 0; e < NEXP; e++)
            if (e != i0 && acc[e] > acc[i1]) i1 = e;
        float m2 = fmaxf(acc[i0], acc[i1]);
        float e0 = __expf(acc[i0] - m2), e1 = __expf(acc[i1] - m2);
        float inv2 = 1.f / (e0 + e1);
        g_topi[2 * gwarp]     = i0; g_topw[2 * gwarp]     = e0 * inv2;
        g_topi[2 * gwarp + 1] = i1; g_topw[2 * gwarp + 1] = e1 * inv2;
        atomicAdd(&g_cnt[i0], 1);
        atomicAdd(&g_cnt[i1], 1);
    }
}

__global__ void k_offsets(float* __restrict__ out) {
    if (threadIdx.x != 0 || blockIdx.x != 0) return;
    int off = 0;
    for (int e = 0; e < NEXP; e++) {
        g_offpad[e] = off;
        off += ((g_cnt[e] + BM - 1) / BM) * BM;
    }
    g_offpad[NEXP] = off;
    float loss = 0.f;
    const float invT = 1.f / (float)T_TOK;
    for (int e = 0; e < NEXP; e++) {
        float m = g_probsum[e] * invT;
        out[(size_t)T_TOK * DIM + 1 + e] = m;
        loss += m * m;
    }
    out[(size_t)T_TOK * DIM] = (float)NEXP * loss;
}

__global__ void k_scatter() {
    int t = blockIdx.x * blockDim.x + threadIdx.x;
    if (t >= 2 * T_TOK) return;
    int e = g_topi[t];
    int pos = g_offpad[e] + atomicAdd(&g_cursor[e], 1);
    g_perm[pos]  = t >> 1;
    g_permw[pos] = g_topw[t];
}

// ---------------- GEMM1 core (gate or up), fp16 MMA, BK=64, 3-stage ------------
template<int UP>
__device__ __forceinline__ void gemm1_body(const __half* __restrict__ wT) {
    extern __shared__ __half smh[];
    int total = g_offpad[NEXP];
    int mbase = blockIdx.y * BM;
    if (mbase >= total) return;
    int e = 0;
#pragma unroll
    for (int i = 0; i < NEXP; i++) if (mbase >= g_offpad[i + 1]) e = i + 1;

    const __half* W = wT + (size_t)e * DIM * HID;   // [n=HID][k=DIM]
    int ncol = blockIdx.x * BN;

    int tid = threadIdx.x;
    uint32_t smb = smem_u32(smh);

    int row0 = tid >> 3, chk = (tid & 7) * 8;
    uint32_t adst[4], bdst[4];
    const __half *asrc[4], *bsrc[4];
    uint32_t asz[4];
#pragma unroll
    for (int p = 0; p < 4; p++) {
        int row = row0 + p * 32;
        adst[p] = (uint32_t)((row * SAH + chk) * 2);
        bdst[p] = (uint32_t)((ATILEH + row * SAH + chk) * 2);
        int tok = g_perm[mbase + row];
        asrc[p] = g_xh + ((tok >= 0) ? (size_t)tok * DIM : 0) + chk;
        asz[p]  = (tok >= 0) ? 16u : 0u;
        bsrc[p] = W + (size_t)(ncol + row) * DIM + chk;
    }

    int lane = tid & 31, gid = lane >> 2, tig = lane & 3;
    int wm = (tid >> 5) & 3, wn = tid >> 7;
    uint32_t aln = (uint32_t)(((wm * 32 + (lane & 15)) * SAH + (lane >> 4) * 8) * 2);
    uint32_t bln = (uint32_t)((ATILEH +
        (wn * 64 + (lane & 7) + ((lane >> 4) << 3)) * SAH +
        ((lane >> 3) & 1) * 8) * 2);

    float acc[2][8][4];
#pragma unroll
    for (int mt = 0; mt < 2; mt++)
#pragma unroll
        for (int nt = 0; nt < 8; nt++)
#pragma unroll
            for (int q = 0; q < 4; q++) acc[mt][nt][q] = 0.f;

    const int NT = DIM / BK;             // 16
#pragma unroll
    for (int t = 0; t < 2; t++) {
        uint32_t base = smb + t * STGB;
        int k0 = t * BK;
#pragma unroll
        for (int p = 0; p < 4; p++) cp16h(base + adst[p], asrc[p] + k0, asz[p]);
#pragma unroll
        for (int p = 0; p < 4; p++) cp16h(base + bdst[p], bsrc[p] + k0, 16);
        CP_COMMIT();
    }

    for (int i = 0; i < NT; i++) {
        CP_WAIT1();
        __syncthreads();
        int t = i + 2;
        if (t < NT) {
            uint32_t base = smb + (t % NSTG) * STGB;
            int k0 = t * BK;
#pragma unroll
            for (int p = 0; p < 4; p++) cp16h(base + adst[p], asrc[p] + k0, asz[p]);
#pragma unroll
            for (int p = 0; p < 4; p++) cp16h(base + bdst[p], bsrc[p] + k0, 16);
        }
        CP_COMMIT();

        uint32_t stg = smb + (uint32_t)(i % NSTG) * STGB;
#pragma unroll
        for (int ks = 0; ks < 4; ks++) {
            uint32_t a[2][4], b[4][4];
#pragma unroll
            for (int mt = 0; mt < 2; mt++)
                ldsm_x4(a[mt], stg + aln + (uint32_t)(mt * 16 * SAH * 2 + ks * 32));
#pragma unroll
            for (int j = 0; j < 4; j++)
                ldsm_x4(b[j], stg + bln + (uint32_t)(j * 16 * SAH * 2 + ks * 32));
#pragma unroll
            for (int mt = 0; mt < 2; mt++)
#pragma unroll
                for (int j = 0; j < 4; j++) {
                    mma_f16(acc[mt][2 * j],     a[mt], &b[j][0]);
                    mma_f16(acc[mt][2 * j + 1], a[mt], &b[j][2]);
                }
        }
    }

#pragma unroll
    for (int mt = 0; mt < 2; mt++) {
        int r = mbase + wm * 32 + mt * 16 + gid;
#pragma unroll
        for (int nt = 0; nt < 8; nt++) {
            int c = ncol + wn * 64 + nt * 8 + 2 * tig;
            if (UP) {
                float2 ga = __half22float2(*(__half2*)&g_gh[(size_t)r * HID + c]);
                float2 gb = __half22float2(*(__half2*)&g_gh[(size_t)(r + 8) * HID + c]);
                float h0 = ga.x * (1.f / (1.f + __expf(-ga.x))) * acc[mt][nt][0];
                float h1 = ga.y * (1.f / (1.f + __expf(-ga.y))) * acc[mt][nt][1];
                float h2 = gb.x * (1.f / (1.f + __expf(-gb.x))) * acc[mt][nt][2];
                float h3 = gb.y * (1.f / (1.f + __expf(-gb.y))) * acc[mt][nt][3];
                *(__half2*)&g_hh[(size_t)r * HID + c]       = __floats2half2_rn(h0, h1);
                *(__half2*)&g_hh[(size_t)(r + 8) * HID + c] = __floats2half2_rn(h2, h3);
            } else {
                *(__half2*)&g_gh[(size_t)r * HID + c] =
                    __floats2half2_rn(acc[mt][nt][0], acc[mt][nt][1]);
                *(__half2*)&g_gh[(size_t)(r + 8) * HID + c] =
                    __floats2half2_rn(acc[mt][nt][2], acc[mt][nt][3]);
            }
        }
    }
}

__global__ __launch_bounds__(256) void k_g1gate() { gemm1_body<0>(g_wgT); }
__global__ __launch_bounds__(256) void k_g1up()   { gemm1_body<1>(g_wuT); }

// ---------------- GEMM2: A = g_hh fp16, B = g_wdT fp16, atomic epilogue --------
__global__ __launch_bounds__(256) void k_gemm2_mma(float* __restrict__ out) {
    extern __shared__ __half smh[];
    int total = g_offpad[NEXP];
    int mbase = blockIdx.y * BM;
    if (mbase >= total) return;
    int e = 0;
#pragma unroll
    for (int i = 0; i < NEXP; i++) if (mbase >= g_offpad[i + 1]) e = i + 1;

    const __half* W = g_wdT + (size_t)e * DIM * HID;   // [n=DIM][k=HID]
    int ncol = blockIdx.x * BN;

    int tid = threadIdx.x;
    uint32_t smb = smem_u32(smh);

    int row0 = tid >> 3, chk = (tid & 7) * 8;
    uint32_t adst[4], bdst[4];
    const __half *asrc[4], *bsrc[4];
#pragma unroll
    for (int p = 0; p < 4; p++) {
        int row = row0 + p * 32;
        adst[p] = (uint32_t)((row * SAH + chk) * 2);
        bdst[p] = (uint32_t)((ATILEH + row * SAH + chk) * 2);
        asrc[p] = g_hh + (size_t)(mbase + row) * HID + chk;
        bsrc[p] = W + (size_t)(ncol + row) * HID + chk;
    }

    int lane = tid & 31, gid = lane >> 2, tig = lane & 3;
    int wm = (tid >> 5) & 3, wn = tid >> 7;
    uint32_t aln = (uint32_t)(((wm * 32 + (lane & 15)) * SAH + (lane >> 4) * 8) * 2);
    uint32_t bln = (uint32_t)((ATILEH +
        (wn * 64 + (lane & 7) + ((lane >> 4) << 3)) * SAH +
        ((lane >> 3) & 1) * 8) * 2);

    float acc[2][8][4];
#pragma unroll
    for (int mt = 0; mt < 2; mt++)
#pragma unroll
        for (int nt = 0; nt < 8; nt++)
#pragma unroll
            for (int q = 0; q < 4; q++) acc[mt][nt][q] = 0.f;

    const int NT = HID / BK;            // 64
#pragma unroll
    for (int t = 0; t < 2; t++) {
        uint32_t base = smb + t * STGB;
        int k0 = t * BK;
#pragma unroll
        for (int p = 0; p < 4; p++) cp16h(base + adst[p], asrc[p] + k0, 16);
#pragma unroll
        for (int p = 0; p < 4; p++) cp16h(base + bdst[p], bsrc[p] + k0, 16);
        CP_COMMIT();
    }

    for (int i = 0; i < NT; i++) {
        CP_WAIT1();
        __syncthreads();
        int t = i + 2;
        if (t < NT) {
            uint32_t base = smb + (t % NSTG) * STGB;
            int k0 = t * BK;
#pragma unroll
            for (int p = 0; p < 4; p++) cp16h(base + adst[p], asrc[p] + k0, 16);
#pragma unroll
            for (int p = 0; p < 4; p++) cp16h(base + bdst[p], bsrc[p] + k0, 16);
        }
        CP_COMMIT();

        uint32_t stg = smb + (uint32_t)(i % NSTG) * STGB;
#pragma unroll
        for (int ks = 0; ks < 4; ks++) {
            uint32_t a[2][4], b[4][4];
#pragma unroll
            for (int mt = 0; mt < 2; mt++)
                ldsm_x4(a[mt], stg + aln + (uint32_t)(mt * 16 * SAH * 2 + ks * 32));
#pragma unroll
            for (int j = 0; j < 4; j++)
                ldsm_x4(b[j], stg + bln + (uint32_t)(j * 16 * SAH * 2 + ks * 32));
#pragma unroll
            for (int mt = 0; mt < 2; mt++)
#pragma unroll
                for (int j = 0; j < 4; j++) {
                    mma_f16(acc[mt][2 * j],     a[mt], &b[j][0]);
                    mma_f16(acc[mt][2 * j + 1], a[mt], &b[j][2]);
                }
        }
    }

#pragma unroll
    for (int mt = 0; mt < 2; mt++) {
        int slot = mbase + wm * 32 + mt * 16 + gid;
        int tok0 = g_perm[slot],     tok1 = g_perm[slot + 8];
        float w0 = g_permw[slot],    w1 = g_permw[slot + 8];
#pragma unroll
        for (int nt = 0; nt < 8; nt++) {
            int c = ncol + wn * 64 + nt * 8 + 2 * tig;
            if (tok0 >= 0) {
                float* op = out + (size_t)tok0 * DIM + c;
                atomicAdd(op,     w0 * acc[mt][nt][0]);
                atomicAdd(op + 1, w0 * acc[mt][nt][1]);
            }
            if (tok1 >= 0) {
                float* op = out + (size_t)tok1 * DIM + c;
                atomicAdd(op,     w1 * acc[mt][nt][2]);
                atomicAdd(op + 1, w1 * acc[mt][nt][3]);
            }
        }
    }
}

// ---------------- launch: fork-join streams ----------------
extern "C" void kernel_launch(void* const* d_in, const int* in_sizes, int n_in,
                              void* d_out, int out_size) {
    const float* x      = (const float*)d_in[0];
    const float* gate_w = (const float*)d_in[1];
    const float* w_gate = (const float*)d_in[2];
    const float* w_up   = (const float*)d_in[3];
    const float* w_down = (const float*)d_in[4];
    float* out = (float*)d_out;

    static bool inited = false;
    static cudaStream_t s1, s2;
    static cudaEvent_t eF, eWg, eWu, eWd, eZ, eP;
    static void* p_perm = nullptr;
    if (!inited) {
        cudaFuncSetAttribute(k_g1gate, cudaFuncAttributeMaxDynamicSharedMemorySize,
                             SMEM_DYN);
        cudaFuncSetAttribute(k_g1up, cudaFuncAttributeMaxDynamicSharedMemorySize,
                             SMEM_DYN);
        cudaFuncSetAttribute(k_gemm2_mma, cudaFuncAttributeMaxDynamicSharedMemorySize,
                             SMEM_DYN);
        cudaStreamCreateWithFlags(&s1, cudaStreamNonBlocking);
        cudaStreamCreateWithFlags(&s2, cudaStreamNonBlocking);
        cudaEventCreateWithFlags(&eF,  cudaEventDisableTiming);
        cudaEventCreateWithFlags(&eWg, cudaEventDisableTiming);
        cudaEventCreateWithFlags(&eWu, cudaEventDisableTiming);
        cudaEventCreateWithFlags(&eWd, cudaEventDisableTiming);
        cudaEventCreateWithFlags(&eZ,  cudaEventDisableTiming);
        cudaEventCreateWithFlags(&eP,  cudaEventDisableTiming);
        cudaGetSymbolAddress(&p_perm, g_perm);
        inited = true;
    }

    // fork
    cudaEventRecord(eF, 0);
    cudaStreamWaitEvent(s1, eF, 0);
    cudaStreamWaitEvent(s2, eF, 0);

    // s1: weight transposes (independent of routing chain)
    dim3 trb(32, 8);
    k_tr<<<dim3(HID / 64, DIM / 64, NEXP), trb, 0, s1>>>(w_gate, DIM, HID, 0);
    cudaEventRecord(eWg, s1);
    k_tr<<<dim3(HID / 64, DIM / 64, NEXP), trb, 0, s1>>>(w_up,   DIM, HID, 1);
    cudaEventRecord(eWu, s1);
    k_tr<<<dim3(DIM / 64, HID / 64, NEXP), trb, 0, s1>>>(w_down, HID, DIM, 2);
    cudaEventRecord(eWd, s1);

    // s2: perm fill (-1 = 0xFF bytes) + output zeroing
    cudaMemsetAsync(p_perm, 0xFF, (size_t)MAXPAD * sizeof(int), s2);
    cudaEventRecord(eP, s2);
    k_zero_out<<<2048, 256, 0, s2>>>((float4*)out, (T_TOK * DIM) / 4);
    cudaEventRecord(eZ, s2);

    // main: routing chain
    k_init0<<<1, 32>>>();
    k_gate<<<T_TOK / 8, 256>>>(x, gate_w);
    k_offsets<<<1, 32>>>(out);
    cudaStreamWaitEvent(0, eP, 0);
    k_scatter<<<(2 * T_TOK) / 256, 256>>>();

    // join + GEMMs
    cudaStreamWaitEvent(0, eWg, 0);
    k_g1gate<<<dim3(HID / BN, NMPAD), 256, SMEM_DYN>>>();
    cudaStreamWaitEvent(0, eWu, 0);
    k_g1up<<<dim3(HID / BN, NMPAD), 256, SMEM_DYN>>>();
    cudaStreamWaitEvent(0, eWd, 0);
    cudaStreamWaitEvent(0, eZ, 0);
    k_gemm2_mma<<<dim3(DIM / BN, NMPAD), 256, SMEM_DYN>>>(out);
}

// round 16
// speedup vs baseline: 1.0071x; 1.0071x over previous
#include <cuda_runtime.h>
#include <cuda_fp16.h>
#include <cstdint>

#define T_TOK 8192
#define DIM   1024
#define HID   4096
#define NEXP  8
#define BM 128
#define BN 128
#define BK 64                      // k elements per stage (fp16)
#define NMPAD  136
#define MAXPAD (NMPAD * BM)
#define HALFY  (NMPAD / 2)         // 68

#define SAH 72                     // smem row stride in halves (144 bytes)
#define ATILEH (BM * SAH)          // 9216 halves per tile
#define STGB (2 * ATILEH * 2)      // 36864 bytes per stage (A+B)
#define NSTG 3
#define SMEM_DYN (NSTG * STGB)     // 110592 bytes -> 2 CTAs/SM

// ---------------- scratch ----------------
__device__ __half g_gh[(size_t)MAXPAD * HID];      // raw gate g in fp16
__device__ __half g_hh[(size_t)MAXPAD * HID];      // h = silu(g)*u in fp16
__device__ __half g_xh[(size_t)T_TOK * DIM];       // x in fp16
__device__ __half g_wgT[(size_t)NEXP * HID * DIM]; // w_gate^T [e][n][k] fp16
__device__ __half g_wuT[(size_t)NEXP * HID * DIM];
__device__ __half g_wdT[(size_t)NEXP * DIM * HID];
__device__ int    g_perm[MAXPAD];
__device__ float  g_permw[MAXPAD];
__device__ int    g_offpad[NEXP + 1];
__device__ int    g_cnt[NEXP];
__device__ int    g_cursor[NEXP];
__device__ float  g_probsum[NEXP];
__device__ int    g_topi[T_TOK * 2];
__device__ float  g_topw[T_TOK * 2];

// ---------------- helpers ----------------
__device__ __forceinline__ uint32_t smem_u32(const void* p) {
    uint32_t a;
    asm("{ .reg .u64 t; cvta.to.shared.u64 t, %1; cvt.u32.u64 %0, t; }"
        : "=r"(a) : "l"(p));
    return a;
}
__device__ __forceinline__ void cp16h(uint32_t d, const __half* s, uint32_t sz) {
    asm volatile("cp.async.cg.shared.global [%0], [%1], 16, %2;"
                 :: "r"(d), "l"(s), "r"(sz));
}
#define CP_COMMIT() asm volatile("cp.async.commit_group;" ::: "memory")
#define CP_WAIT1()  asm volatile("cp.async.wait_group 1;" ::: "memory")

__device__ __forceinline__ void mma_f16(float* c, const uint32_t* a,
                                        const uint32_t* b) {
    asm volatile(
        "mma.sync.aligned.m16n8k16.row.col.f32.f16.f16.f32 "
        "{%0,%1,%2,%3}, {%4,%5,%6,%7}, {%8,%9}, {%0,%1,%2,%3};"
        : "+f"(c[0]), "+f"(c[1]), "+f"(c[2]), "+f"(c[3])
        : "r"(a[0]), "r"(a[1]), "r"(a[2]), "r"(a[3]), "r"(b[0]), "r"(b[1]));
}

__device__ __forceinline__ void ldsm_x4(uint32_t* r, uint32_t addr) {
    asm volatile("ldmatrix.sync.aligned.m8n8.x4.shared.b16 {%0,%1,%2,%3}, [%4];"
                 : "=r"(r[0]), "=r"(r[1]), "=r"(r[2]), "=r"(r[3]) : "r"(addr));
}

// ---------------- small kernels ----------------
__global__ void k_init() {
    int i = blockIdx.x * blockDim.x + threadIdx.x;
    if (i < NEXP) { g_cnt[i] = 0; g_cursor[i] = 0; g_probsum[i] = 0.f; }
    if (i < MAXPAD) g_perm[i] = -1;
}

__global__ void k_zero_out(float4* out, int n4) {
    float4 z = make_float4(0.f, 0.f, 0.f, 0.f);
    for (int i = blockIdx.x * blockDim.x + threadIdx.x; i < n4;
         i += gridDim.x * blockDim.x)
        out[i] = z;
}

// transpose+convert: src fp32 [e][R][C] -> dst fp16 [e][C][R], 64x64 tiles
__global__ void k_tr(const float* __restrict__ src, int R, int C, int sel) {
    __half* dstb = (sel == 0) ? g_wgT : (sel == 1) ? g_wuT : g_wdT;
    __shared__ float t[64][65];
    size_t mo = (size_t)blockIdx.z * R * C;
    const float* s = src + mo;
    __half* d = dstb + mo;
    int c0 = blockIdx.x * 64, r0 = blockIdx.y * 64;
    int tx = threadIdx.x, ty = threadIdx.y;
#pragma unroll
    for (int j = ty; j < 64; j += 8) {
        float2 v = *(const float2*)&s[(size_t)(r0 + j) * C + c0 + tx * 2];
        t[j][tx * 2] = v.x; t[j][tx * 2 + 1] = v.y;
    }
    __syncthreads();
#pragma unroll
    for (int j = ty; j < 64; j += 8) {
        __half2 h = __floats2half2_rn(t[tx * 2][j], t[tx * 2 + 1][j]);
        *(__half2*)&d[(size_t)(c0 + j) * R + r0 + tx * 2] = h;
    }
}

// gating + fused x->fp16 conversion (R13 scalar version — measured best)
__global__ void k_gate(const float* __restrict__ x, const float* __restrict__ gw) {
    int gwarp = (blockIdx.x * blockDim.x + threadIdx.x) >> 5;
    int lane  = threadIdx.x & 31;
    if (gwarp >= T_TOK) return;
    const float* xr = x + (size_t)gwarp * DIM;
    __half* xh = g_xh + (size_t)gwarp * DIM;

    float acc[NEXP];
#pragma unroll
    for (int e = 0; e < NEXP; e++) acc[e] = 0.f;
    for (int i = lane; i < DIM; i += 32) {
        float xv = xr[i];
        xh[i] = __float2half_rn(xv);
        float4 g0 = *(const float4*)(gw + (size_t)i * NEXP);
        float4 g1 = *(const float4*)(gw + (size_t)i * NEXP + 4);
        acc[0] += xv * g0.x; acc[1] += xv * g0.y;
        acc[2] += xv * g0.z; acc[3] += xv * g0.w;
        acc[4] += xv * g1.x; acc[5] += xv * g1.y;
        acc[6] += xv * g1.z; acc[7] += xv * g1.w;
    }
#pragma unroll
    for (int off = 16; off > 0; off >>= 1)
#pragma unroll
        for (int e = 0; e < NEXP; e++)
            acc[e] += __shfl_xor_sync(0xffffffffu, acc[e], off);

    float mx = acc[0];
#pragma unroll
    for (int e = 1; e < NEXP; e++) mx = fmaxf(mx, acc[e]);
    float p[NEXP], s = 0.f;
#pragma unroll
    for (int e = 0; e < NEXP; e++) { p[e] = __expf(acc[e] - mx); s += p[e]; }
    float inv = 1.f / s;
    if (lane < NEXP) atomicAdd(&g_probsum[lane], p[lane] * inv);

    if (lane == 0) {
        int i0 = 0;
#pragma unroll
        for (int e = 1; e < NEXP; e++) if (acc[e] > acc[i0]) i0 = e;
        int i1 = (i0 == 0) ? 1 : 0;
#pragma unroll
        for (int e = 0; e < NEXP; e++)
            if (e != i0 && acc[e] > acc[i1]) i1 = e;
        float m2 = fmaxf(acc[i0], acc[i1]);
        float e0 = __expf(acc[i0] - m2), e1 = __expf(acc[i1] - m2);
        float inv2 = 1.f / (e0 + e1);
        g_topi[2 * gwarp]     = i0; g_topw[2 * gwarp]     = e0 * inv2;
        g_topi[2 * gwarp + 1] = i1; g_topw[2 * gwarp + 1] = e1 * inv2;
        atomicAdd(&g_cnt[i0], 1);
        atomicAdd(&g_cnt[i1], 1);
    }
}

__global__ void k_offsets(float* __restrict__ out) {
    if (threadIdx.x != 0 || blockIdx.x != 0) return;
    int off = 0;
    for (int e = 0; e < NEXP; e++) {
        g_offpad[e] = off;
        off += ((g_cnt[e] + BM - 1) / BM) * BM;
    }
    g_offpad[NEXP] = off;
    float loss = 0.f;
    const float invT = 1.f / (float)T_TOK;
    for (int e = 0; e < NEXP; e++) {
        float m = g_probsum[e] * invT;
        out[(size_t)T_TOK * DIM + 1 + e] = m;
        loss += m * m;
    }
    out[(size_t)T_TOK * DIM] = (float)NEXP * loss;
}

__global__ void k_scatter() {
    int t = blockIdx.x * blockDim.x + threadIdx.x;
    if (t >= 2 * T_TOK) return;
    int e = g_topi[t];
    int pos = g_offpad[e] + atomicAdd(&g_cursor[e], 1);
    g_perm[pos]  = t >> 1;
    g_permw[pos] = g_topw[t];
}

// ---------------- GEMM1 core (gate or up), fp16 MMA, BK=64, 3-stage ------------
// ybase: M-tile offset (half-split pipelining across streams).
template<int UP>
__device__ __forceinline__ void gemm1_body(const __half* __restrict__ wT,
                                           int ybase) {
    extern __shared__ __half smh[];
    int total = g_offpad[NEXP];
    int mbase = (ybase + blockIdx.y) * BM;
    if (mbase >= total) return;
    int e = 0;
#pragma unroll
    for (int i = 0; i < NEXP; i++) if (mbase >= g_offpad[i + 1]) e = i + 1;

    const __half* W = wT + (size_t)e * DIM * HID;   // [n=HID][k=DIM]
    int ncol = blockIdx.x * BN;

    int tid = threadIdx.x;
    uint32_t smb = smem_u32(smh);

    int row0 = tid >> 3, chk = (tid & 7) * 8;
    uint32_t adst[4], bdst[4];
    const __half *asrc[4], *bsrc[4];
    uint32_t asz[4];
#pragma unroll
    for (int p = 0; p < 4; p++) {
        int row = row0 + p * 32;
        adst[p] = (uint32_t)((row * SAH + chk) * 2);
        bdst[p] = (uint32_t)((ATILEH + row * SAH + chk) * 2);
        int tok = g_perm[mbase + row];
        asrc[p] = g_xh + ((tok >= 0) ? (size_t)tok * DIM : 0) + chk;
        asz[p]  = (tok >= 0) ? 16u : 0u;
        bsrc[p] = W + (size_t)(ncol + row) * DIM + chk;
    }

    int lane = tid & 31, gid = lane >> 2, tig = lane & 3;
    int wm = (tid >> 5) & 3, wn = tid >> 7;
    uint32_t aln = (uint32_t)(((wm * 32 + (lane & 15)) * SAH + (lane >> 4) * 8) * 2);
    uint32_t bln = (uint32_t)((ATILEH +
        (wn * 64 + (lane & 7) + ((lane >> 4) << 3)) * SAH +
        ((lane >> 3) & 1) * 8) * 2);

    float acc[2][8][4];
#pragma unroll
    for (int mt = 0; mt < 2; mt++)
#pragma unroll
        for (int nt = 0; nt < 8; nt++)
#pragma unroll
            for (int q = 0; q < 4; q++) acc[mt][nt][q] = 0.f;

    const int NT = DIM / BK;             // 16
#pragma unroll
    for (int t = 0; t < 2; t++) {
        uint32_t base = smb + t * STGB;
        int k0 = t * BK;
#pragma unroll
        for (int p = 0; p < 4; p++) cp16h(base + adst[p], asrc[p] + k0, asz[p]);
#pragma unroll
        for (int p = 0; p < 4; p++) cp16h(base + bdst[p], bsrc[p] + k0, 16);
        CP_COMMIT();
    }

    for (int i = 0; i < NT; i++) {
        CP_WAIT1();
        __syncthreads();
        int t = i + 2;
        if (t < NT) {
            uint32_t base = smb + (t % NSTG) * STGB;
            int k0 = t * BK;
#pragma unroll
            for (int p = 0; p < 4; p++) cp16h(base + adst[p], asrc[p] + k0, asz[p]);
#pragma unroll
            for (int p = 0; p < 4; p++) cp16h(base + bdst[p], bsrc[p] + k0, 16);
        }
        CP_COMMIT();

        uint32_t stg = smb + (uint32_t)(i % NSTG) * STGB;
#pragma unroll
        for (int ks = 0; ks < 4; ks++) {
            uint32_t a[2][4], b[4][4];
#pragma unroll
            for (int mt = 0; mt < 2; mt++)
                ldsm_x4(a[mt], stg + aln + (uint32_t)(mt * 16 * SAH * 2 + ks * 32));
#pragma unroll
            for (int j = 0; j < 4; j++)
                ldsm_x4(b[j], stg + bln + (uint32_t)(j * 16 * SAH * 2 + ks * 32));
#pragma unroll
            for (int mt = 0; mt < 2; mt++)
#pragma unroll
                for (int j = 0; j < 4; j++) {
                    mma_f16(acc[mt][2 * j],     a[mt], &b[j][0]);
                    mma_f16(acc[mt][2 * j + 1], a[mt], &b[j][2]);
                }
        }
    }

#pragma unroll
    for (int mt = 0; mt < 2; mt++) {
        int r = mbase + wm * 32 + mt * 16 + gid;
#pragma unroll
        for (int nt = 0; nt < 8; nt++) {
            int c = ncol + wn * 64 + nt * 8 + 2 * tig;
            if (UP) {
                float2 ga = __half22float2(*(__half2*)&g_gh[(size_t)r * HID + c]);
                float2 gb = __half22float2(*(__half2*)&g_gh[(size_t)(r + 8) * HID + c]);
                float h0 = ga.x * (1.f / (1.f + __expf(-ga.x))) * acc[mt][nt][0];
                float h1 = ga.y * (1.f / (1.f + __expf(-ga.y))) * acc[mt][nt][1];
                float h2 = gb.x * (1.f / (1.f + __expf(-gb.x))) * acc[mt][nt][2];
                float h3 = gb.y * (1.f / (1.f + __expf(-gb.y))) * acc[mt][nt][3];
                *(__half2*)&g_hh[(size_t)r * HID + c]       = __floats2half2_rn(h0, h1);
                *(__half2*)&g_hh[(size_t)(r + 8) * HID + c] = __floats2half2_rn(h2, h3);
            } else {
                *(__half2*)&g_gh[(size_t)r * HID + c] =
                    __floats2half2_rn(acc[mt][nt][0], acc[mt][nt][1]);
                *(__half2*)&g_gh[(size_t)(r + 8) * HID + c] =
                    __floats2half2_rn(acc[mt][nt][2], acc[mt][nt][3]);
            }
        }
    }
}

__global__ __launch_bounds__(256) void k_g1gate(int ybase) {
    gemm1_body<0>(g_wgT, ybase);
}
__global__ __launch_bounds__(256) void k_g1up(int ybase) {
    gemm1_body<1>(g_wuT, ybase);
}

// ---------------- GEMM2: A = g_hh fp16, B = g_wdT fp16, atomic epilogue --------
__global__ __launch_bounds__(256) void k_gemm2_mma(float* __restrict__ out) {
    extern __shared__ __half smh[];
    int total = g_offpad[NEXP];
    int mbase = blockIdx.y * BM;
    if (mbase >= total) return;
    int e = 0;
#pragma unroll
    for (int i = 0; i < NEXP; i++) if (mbase >= g_offpad[i + 1]) e = i + 1;

    const __half* W = g_wdT + (size_t)e * DIM * HID;   // [n=DIM][k=HID]
    int ncol = blockIdx.x * BN;

    int tid = threadIdx.x;
    uint32_t smb = smem_u32(smh);

    int row0 = tid >> 3, chk = (tid & 7) * 8;
    uint32_t adst[4], bdst[4];
    const __half *asrc[4], *bsrc[4];
#pragma unroll
    for (int p = 0; p < 4; p++) {
        int row = row0 + p * 32;
        adst[p] = (uint32_t)((row * SAH + chk) * 2);
        bdst[p] = (uint32_t)((ATILEH + row * SAH + chk) * 2);
        asrc[p] = g_hh + (size_t)(mbase + row) * HID + chk;
        bsrc[p] = W + (size_t)(ncol + row) * HID + chk;
    }

    int lane = tid & 31, gid = lane >> 2, tig = lane & 3;
    int wm = (tid >> 5) & 3, wn = tid >> 7;
    uint32_t aln = (uint32_t)(((wm * 32 + (lane & 15)) * SAH + (lane >> 4) * 8) * 2);
    uint32_t bln = (uint32_t)((ATILEH +
        (wn * 64 + (lane & 7) + ((lane >> 4) << 3)) * SAH +
        ((lane >> 3) & 1) * 8) * 2);

    float acc[2][8][4];
#pragma unroll
    for (int mt = 0; mt < 2; mt++)
#pragma unroll
        for (int nt = 0; nt < 8; nt++)
#pragma unroll
            for (int q = 0; q < 4; q++) acc[mt][nt][q] = 0.f;

    const int NT = HID / BK;            // 64
#pragma unroll
    for (int t = 0; t < 2; t++) {
        uint32_t base = smb + t * STGB;
        int k0 = t * BK;
#pragma unroll
        for (int p = 0; p < 4; p++) cp16h(base + adst[p], asrc[p] + k0, 16);
#pragma unroll
        for (int p = 0; p < 4; p++) cp16h(base + bdst[p], bsrc[p] + k0, 16);
        CP_COMMIT();
    }

    for (int i = 0; i < NT; i++) {
        CP_WAIT1();
        __syncthreads();
        int t = i + 2;
        if (t < NT) {
            uint32_t base = smb + (t % NSTG) * STGB;
            int k0 = t * BK;
#pragma unroll
            for (int p = 0; p < 4; p++) cp16h(base + adst[p], asrc[p] + k0, 16);
#pragma unroll
            for (int p = 0; p < 4; p++) cp16h(base + bdst[p], bsrc[p] + k0, 16);
        }
        CP_COMMIT();

        uint32_t stg = smb + (uint32_t)(i % NSTG) * STGB;
#pragma unroll
        for (int ks = 0; ks < 4; ks++) {
            uint32_t a[2][4], b[4][4];
#pragma unroll
            for (int mt = 0; mt < 2; mt++)
                ldsm_x4(a[mt], stg + aln + (uint32_t)(mt * 16 * SAH * 2 + ks * 32));
#pragma unroll
            for (int j = 0; j < 4; j++)
                ldsm_x4(b[j], stg + bln + (uint32_t)(j * 16 * SAH * 2 + ks * 32));
#pragma unroll
            for (int mt = 0; mt < 2; mt++)
#pragma unroll
                for (int j = 0; j < 4; j++) {
                    mma_f16(acc[mt][2 * j],     a[mt], &b[j][0]);
                    mma_f16(acc[mt][2 * j + 1], a[mt], &b[j][2]);
                }
        }
    }

#pragma unroll
    for (int mt = 0; mt < 2; mt++) {
        int slot = mbase + wm * 32 + mt * 16 + gid;
        int tok0 = g_perm[slot],     tok1 = g_perm[slot + 8];
        float w0 = g_permw[slot],    w1 = g_permw[slot + 8];
#pragma unroll
        for (int nt = 0; nt < 8; nt++) {
            int c = ncol + wn * 64 + nt * 8 + 2 * tig;
            if (tok0 >= 0) {
                float* op = out + (size_t)tok0 * DIM + c;
                atomicAdd(op,     w0 * acc[mt][nt][0]);
                atomicAdd(op + 1, w0 * acc[mt][nt][1]);
            }
            if (tok1 >= 0) {
                float* op = out + (size_t)tok1 * DIM + c;
                atomicAdd(op,     w1 * acc[mt][nt][2]);
                atomicAdd(op + 1, w1 * acc[mt][nt][3]);
            }
        }
    }
}

// ---------------- launch: fork-join + half-split GEMM1 pipelining ----------------
extern "C" void kernel_launch(void* const* d_in, const int* in_sizes, int n_in,
                              void* d_out, int out_size) {
    const float* x      = (const float*)d_in[0];
    const float* gate_w = (const float*)d_in[1];
    const float* w_gate = (const float*)d_in[2];
    const float* w_up   = (const float*)d_in[3];
    const float* w_down = (const float*)d_in[4];
    float* out = (float*)d_out;

    static bool inited = false;
    static cudaStream_t s1, s2;
    static cudaEvent_t eF, eWg, eWu, eWd, eZ, eG0, eG1, eU;
    if (!inited) {
        cudaFuncSetAttribute(k_g1gate, cudaFuncAttributeMaxDynamicSharedMemorySize,
                             SMEM_DYN);
        cudaFuncSetAttribute(k_g1up, cudaFuncAttributeMaxDynamicSharedMemorySize,
                             SMEM_DYN);
        cudaFuncSetAttribute(k_gemm2_mma, cudaFuncAttributeMaxDynamicSharedMemorySize,
                             SMEM_DYN);
        cudaStreamCreateWithFlags(&s1, cudaStreamNonBlocking);
        cudaStreamCreateWithFlags(&s2, cudaStreamNonBlocking);
        cudaEventCreateWithFlags(&eF,  cudaEventDisableTiming);
        cudaEventCreateWithFlags(&eWg, cudaEventDisableTiming);
        cudaEventCreateWithFlags(&eWu, cudaEventDisableTiming);
        cudaEventCreateWithFlags(&eWd, cudaEventDisableTiming);
        cudaEventCreateWithFlags(&eZ,  cudaEventDisableTiming);
        cudaEventCreateWithFlags(&eG0, cudaEventDisableTiming);
        cudaEventCreateWithFlags(&eG1, cudaEventDisableTiming);
        cudaEventCreateWithFlags(&eU,  cudaEventDisableTiming);
        inited = true;
    }

    // fork
    cudaEventRecord(eF, 0);
    cudaStreamWaitEvent(s1, eF, 0);
    cudaStreamWaitEvent(s2, eF, 0);

    // s1: weight transposes (independent of routing chain)
    dim3 trb(32, 8);
    k_tr<<<dim3(HID / 64, DIM / 64, NEXP), trb, 0, s1>>>(w_gate, DIM, HID, 0);
    cudaEventRecord(eWg, s1);
    k_tr<<<dim3(HID / 64, DIM / 64, NEXP), trb, 0, s1>>>(w_up,   DIM, HID, 1);
    cudaEventRecord(eWu, s1);
    k_tr<<<dim3(DIM / 64, HID / 64, NEXP), trb, 0, s1>>>(w_down, HID, DIM, 2);
    cudaEventRecord(eWd, s1);

    // s2: output zeroing (needed only by gemm2), then GEMM1-up halves
    k_zero_out<<<2048, 256, 0, s2>>>((float4*)out, (T_TOK * DIM) / 4);
    cudaEventRecord(eZ, s2);

    // main: routing chain
    k_init<<<MAXPAD / 256, 256>>>();
    k_gate<<<T_TOK / 8, 256>>>(x, gate_w);
    k_offsets<<<1, 32>>>(out);
    k_scatter<<<(2 * T_TOK) / 256, 256>>>();

    // GEMM1 half-split pipeline: gateH0 -> (gateH1 || upH0) -> upH1
    dim3 g1(HID / BN, HALFY);            // 32 x 68
    cudaStreamWaitEvent(0, eWg, 0);
    k_g1gate<<<g1, 256, SMEM_DYN>>>(0);
    cudaEventRecord(eG0, 0);
    k_g1gate<<<g1, 256, SMEM_DYN>>>(HALFY);
    cudaEventRecord(eG1, 0);

    cudaStreamWaitEvent(s2, eWu, 0);
    cudaStreamWaitEvent(s2, eG0, 0);
    k_g1up<<<g1, 256, SMEM_DYN, s2>>>(0);
    cudaStreamWaitEvent(s2, eG1, 0);
    k_g1up<<<g1, 256, SMEM_DYN, s2>>>(HALFY);
    cudaEventRecord(eU, s2);             // also covers eZ (same stream, earlier)

    // join + GEMM2
    cudaStreamWaitEvent(0, eU, 0);
    cudaStreamWaitEvent(0, eWd, 0);
    k_gemm2_mma<<<dim3(DIM / BN, NMPAD), 256, SMEM_DYN>>>(out);
}

// round 17
// speedup vs baseline: 1.0231x; 1.0158x over previous
#include <cuda_runtime.h>
#include <cuda_fp16.h>
#include <cstdint>

#define T_TOK 8192
#define DIM   1024
#define HID   4096
#define NEXP  8
#define BM 128
#define BN 128
#define BK 64                      // k elements per stage (fp16)
#define NMPAD  136
#define MAXPAD (NMPAD * BM)

#define SAH 72                     // smem row stride in halves (144 bytes)
#define ATILEH (BM * SAH)          // 9216 halves per tile
#define STGB (2 * ATILEH * 2)      // 36864 bytes per stage (A+B)
#define NSTG 3
#define SMEM_DYN (NSTG * STGB)     // 110592 bytes -> 2 CTAs/SM

// ---------------- scratch ----------------
__device__ __half g_gh[(size_t)MAXPAD * HID];      // raw gate g in fp16
__device__ __half g_hh[(size_t)MAXPAD * HID];      // h = silu(g)*u in fp16
__device__ __half g_xh[(size_t)T_TOK * DIM];       // x in fp16
__device__ __half g_wgT[(size_t)NEXP * HID * DIM]; // w_gate^T [e][n][k] fp16
__device__ __half g_wuT[(size_t)NEXP * HID * DIM];
__device__ __half g_wdT[(size_t)NEXP * DIM * HID];
__device__ int    g_perm[MAXPAD];
__device__ float  g_permw[MAXPAD];
__device__ int    g_offpad[NEXP + 1];
__device__ int    g_cnt[NEXP];
__device__ int    g_cursor[NEXP];
__device__ float  g_probsum[NEXP];
__device__ int    g_topi[T_TOK * 2];
__device__ float  g_topw[T_TOK * 2];

// ---------------- helpers ----------------
__device__ __forceinline__ uint32_t smem_u32(const void* p) {
    uint32_t a;
    asm("{ .reg .u64 t; cvta.to.shared.u64 t, %1; cvt.u32.u64 %0, t; }"
        : "=r"(a) : "l"(p));
    return a;
}
__device__ __forceinline__ void cp16h(uint32_t d, const __half* s, uint32_t sz) {
    asm volatile("cp.async.cg.shared.global [%0], [%1], 16, %2;"
                 :: "r"(d), "l"(s), "r"(sz));
}
#define CP_COMMIT() asm volatile("cp.async.commit_group;" ::: "memory")
#define CP_WAIT1()  asm volatile("cp.async.wait_group 1;" ::: "memory")

__device__ __forceinline__ void mma_f16(float* c, const uint32_t* a,
                                        const uint32_t* b) {
    asm volatile(
        "mma.sync.aligned.m16n8k16.row.col.f32.f16.f16.f32 "
        "{%0,%1,%2,%3}, {%4,%5,%6,%7}, {%8,%9}, {%0,%1,%2,%3};"
        : "+f"(c[0]), "+f"(c[1]), "+f"(c[2]), "+f"(c[3])
        : "r"(a[0]), "r"(a[1]), "r"(a[2]), "r"(a[3]), "r"(b[0]), "r"(b[1]));
}

__device__ __forceinline__ void ldsm_x4(uint32_t* r, uint32_t addr) {
    asm volatile("ldmatrix.sync.aligned.m8n8.x4.shared.b16 {%0,%1,%2,%3}, [%4];"
                 : "=r"(r[0]), "=r"(r[1]), "=r"(r[2]), "=r"(r[3]) : "r"(addr));
}

// ---------------- small kernels ----------------
__global__ void k_init() {
    int i = blockIdx.x * blockDim.x + threadIdx.x;
    if (i < NEXP) { g_cnt[i] = 0; g_cursor[i] = 0; g_probsum[i] = 0.f; }
    if (i < MAXPAD) g_perm[i] = -1;
}

__global__ void k_zero_out(float4* out, int n4) {
    float4 z = make_float4(0.f, 0.f, 0.f, 0.f);
    for (int i = blockIdx.x * blockDim.x + threadIdx.x; i < n4;
         i += gridDim.x * blockDim.x)
        out[i] = z;
}

// transpose+convert: src fp32 [e][R][C] -> dst fp16 [e][C][R], 64x64 tiles
__global__ void k_tr(const float* __restrict__ src, int R, int C, int sel) {
    __half* dstb = (sel == 0) ? g_wgT : (sel == 1) ? g_wuT : g_wdT;
    __shared__ float t[64][65];
    size_t mo = (size_t)blockIdx.z * R * C;
    const float* s = src + mo;
    __half* d = dstb + mo;
    int c0 = blockIdx.x * 64, r0 = blockIdx.y * 64;
    int tx = threadIdx.x, ty = threadIdx.y;
#pragma unroll
    for (int j = ty; j < 64; j += 8) {
        float2 v = *(const float2*)&s[(size_t)(r0 + j) * C + c0 + tx * 2];
        t[j][tx * 2] = v.x; t[j][tx * 2 + 1] = v.y;
    }
    __syncthreads();
#pragma unroll
    for (int j = ty; j < 64; j += 8) {
        __half2 h = __floats2half2_rn(t[tx * 2][j], t[tx * 2 + 1][j]);
        *(__half2*)&d[(size_t)(c0 + j) * R + r0 + tx * 2] = h;
    }
}

// gating + fused x->fp16 conversion
__global__ void k_gate(const float* __restrict__ x, const float* __restrict__ gw) {
    int gwarp = (blockIdx.x * blockDim.x + threadIdx.x) >> 5;
    int lane  = threadIdx.x & 31;
    if (gwarp >= T_TOK) return;
    const float* xr = x + (size_t)gwarp * DIM;
    __half* xh = g_xh + (size_t)gwarp * DIM;

    float acc[NEXP];
#pragma unroll
    for (int e = 0; e < NEXP; e++) acc[e] = 0.f;
    for (int i = lane; i < DIM; i += 32) {
        float xv = xr[i];
        xh[i] = __float2half_rn(xv);
        float4 g0 = *(const float4*)(gw + (size_t)i * NEXP);
        float4 g1 = *(const float4*)(gw + (size_t)i * NEXP + 4);
        acc[0] += xv * g0.x; acc[1] += xv * g0.y;
        acc[2] += xv * g0.z; acc[3] += xv * g0.w;
        acc[4] += xv * g1.x; acc[5] += xv * g1.y;
        acc[6] += xv * g1.z; acc[7] += xv * g1.w;
    }
#pragma unroll
    for (int off = 16; off > 0; off >>= 1)
#pragma unroll
        for (int e = 0; e < NEXP; e++)
            acc[e] += __shfl_xor_sync(0xffffffffu, acc[e], off);

    float mx = acc[0];
#pragma unroll
    for (int e = 1; e < NEXP; e++) mx = fmaxf(mx, acc[e]);
    float p[NEXP], s = 0.f;
#pragma unroll
    for (int e = 0; e < NEXP; e++) { p[e] = __expf(acc[e] - mx); s += p[e]; }
    float inv = 1.f / s;
    if (lane < NEXP) atomicAdd(&g_probsum[lane], p[lane] * inv);

    if (lane == 0) {
        int i0 = 0;
#pragma unroll
        for (int e = 1; e < NEXP; e++) if (acc[e] > acc[i0]) i0 = e;
        int i1 = (i0 == 0) ? 1 : 0;
#pragma unroll
        for (int e = 0; e < NEXP; e++)
            if (e != i0 && acc[e] > acc[i1]) i1 = e;
        float m2 = fmaxf(acc[i0], acc[i1]);
        float e0 = __expf(acc[i0] - m2), e1 = __expf(acc[i1] - m2);
        float inv2 = 1.f / (e0 + e1);
        g_topi[2 * gwarp]     = i0; g_topw[2 * gwarp]     = e0 * inv2;
        g_topi[2 * gwarp + 1] = i1; g_topw[2 * gwarp + 1] = e1 * inv2;
        atomicAdd(&g_cnt[i0], 1);
        atomicAdd(&g_cnt[i1], 1);
    }
}

__global__ void k_offsets(float* __restrict__ out) {
    if (threadIdx.x != 0 || blockIdx.x != 0) return;
    int off = 0;
    for (int e = 0; e < NEXP; e++) {
        g_offpad[e] = off;
        off += ((g_cnt[e] + BM - 1) / BM) * BM;
    }
    g_offpad[NEXP] = off;
    float loss = 0.f;
    const float invT = 1.f / (float)T_TOK;
    for (int e = 0; e < NEXP; e++) {
        float m = g_probsum[e] * invT;
        out[(size_t)T_TOK * DIM + 1 + e] = m;
        loss += m * m;
    }
    out[(size_t)T_TOK * DIM] = (float)NEXP * loss;
}

__global__ void k_scatter() {
    int t = blockIdx.x * blockDim.x + threadIdx.x;
    if (t >= 2 * T_TOK) return;
    int e = g_topi[t];
    int pos = g_offpad[e] + atomicAdd(&g_cursor[e], 1);
    g_perm[pos]  = t >> 1;
    g_permw[pos] = g_topw[t];
}

// ---------------- GEMM1 core (gate or up), fp16 MMA, BK=64, 3-stage ------------
template<int UP>
__device__ __forceinline__ void gemm1_body(const __half* __restrict__ wT) {
    extern __shared__ __half smh[];
    int total = g_offpad[NEXP];
    int mbase = blockIdx.y * BM;
    if (mbase >= total) return;
    int e = 0;
#pragma unroll
    for (int i = 0; i < NEXP; i++) if (mbase >= g_offpad[i + 1]) e = i + 1;

    const __half* W = wT + (size_t)e * DIM * HID;   // [n=HID][k=DIM]
    int ncol = blockIdx.x * BN;

    int tid = threadIdx.x;
    uint32_t smb = smem_u32(smh);

    int row0 = tid >> 3, chk = (tid & 7) * 8;
    uint32_t adst[4], bdst[4];
    const __half *asrc[4], *bsrc[4];
    uint32_t asz[4];
#pragma unroll
    for (int p = 0; p < 4; p++) {
        int row = row0 + p * 32;
        adst[p] = (uint32_t)((row * SAH + chk) * 2);
        bdst[p] = (uint32_t)((ATILEH + row * SAH + chk) * 2);
        int tok = g_perm[mbase + row];
        asrc[p] = g_xh + ((tok >= 0) ? (size_t)tok * DIM : 0) + chk;
        asz[p]  = (tok >= 0) ? 16u : 0u;
        bsrc[p] = W + (size_t)(ncol + row) * DIM + chk;
    }

    int lane = tid & 31, gid = lane >> 2, tig = lane & 3;
    int wm = (tid >> 5) & 3, wn = tid >> 7;
    uint32_t aln = (uint32_t)(((wm * 32 + (lane & 15)) * SAH + (lane >> 4) * 8) * 2);
    uint32_t bln = (uint32_t)((ATILEH +
        (wn * 64 + (lane & 7) + ((lane >> 4) << 3)) * SAH +
        ((lane >> 3) & 1) * 8) * 2);

    float acc[2][8][4];
#pragma unroll
    for (int mt = 0; mt < 2; mt++)
#pragma unroll
        for (int nt = 0; nt < 8; nt++)
#pragma unroll
            for (int q = 0; q < 4; q++) acc[mt][nt][q] = 0.f;

    const int NT = DIM / BK;             // 16
#pragma unroll
    for (int t = 0; t < 2; t++) {        // prologue: 2 stages
        uint32_t base = smb + t * STGB;
        int k0 = t * BK;
#pragma unroll
        for (int p = 0; p < 4; p++) cp16h(base + adst[p], asrc[p] + k0, asz[p]);
#pragma unroll
        for (int p = 0; p < 4; p++) cp16h(base + bdst[p], bsrc[p] + k0, 16);
        CP_COMMIT();
    }

    for (int i = 0; i < NT; i++) {
        CP_WAIT1();
        __syncthreads();
        int t = i + 2;
        if (t < NT) {
            uint32_t base = smb + (t % NSTG) * STGB;
            int k0 = t * BK;
#pragma unroll
            for (int p = 0; p < 4; p++) cp16h(base + adst[p], asrc[p] + k0, asz[p]);
#pragma unroll
            for (int p = 0; p < 4; p++) cp16h(base + bdst[p], bsrc[p] + k0, 16);
        }
        CP_COMMIT();

        uint32_t stg = smb + (uint32_t)(i % NSTG) * STGB;
#pragma unroll
        for (int ks = 0; ks < 4; ks++) {
            uint32_t a[2][4], b[4][4];
#pragma unroll
            for (int mt = 0; mt < 2; mt++)
                ldsm_x4(a[mt], stg + aln + (uint32_t)(mt * 16 * SAH * 2 + ks * 32));
#pragma unroll
            for (int j = 0; j < 4; j++)
                ldsm_x4(b[j], stg + bln + (uint32_t)(j * 16 * SAH * 2 + ks * 32));
#pragma unroll
            for (int mt = 0; mt < 2; mt++)
#pragma unroll
                for (int j = 0; j < 4; j++) {
                    mma_f16(acc[mt][2 * j],     a[mt], &b[j][0]);
                    mma_f16(acc[mt][2 * j + 1], a[mt], &b[j][2]);
                }
        }
    }

#pragma unroll
    for (int mt = 0; mt < 2; mt++) {
        int r = mbase + wm * 32 + mt * 16 + gid;
#pragma unroll
        for (int nt = 0; nt < 8; nt++) {
            int c = ncol + wn * 64 + nt * 8 + 2 * tig;
            if (UP) {
                float2 ga = __half22float2(*(__half2*)&g_gh[(size_t)r * HID + c]);
                float2 gb = __half22float2(*(__half2*)&g_gh[(size_t)(r + 8) * HID + c]);
                float h0 = ga.x * (1.f / (1.f + __expf(-ga.x))) * acc[mt][nt][0];
                float h1 = ga.y * (1.f / (1.f + __expf(-ga.y))) * acc[mt][nt][1];
                float h2 = gb.x * (1.f / (1.f + __expf(-gb.x))) * acc[mt][nt][2];
                float h3 = gb.y * (1.f / (1.f + __expf(-gb.y))) * acc[mt][nt][3];
                *(__half2*)&g_hh[(size_t)r * HID + c]       = __floats2half2_rn(h0, h1);
                *(__half2*)&g_hh[(size_t)(r + 8) * HID + c] = __floats2half2_rn(h2, h3);
            } else {
                *(__half2*)&g_gh[(size_t)r * HID + c] =
                    __floats2half2_rn(acc[mt][nt][0], acc[mt][nt][1]);
                *(__half2*)&g_gh[(size_t)(r + 8) * HID + c] =
                    __floats2half2_rn(acc[mt][nt][2], acc[mt][nt][3]);
            }
        }
    }
}

__global__ __launch_bounds__(256) void k_g1gate() { gemm1_body<0>(g_wgT); }
__global__ __launch_bounds__(256) void k_g1up()   { gemm1_body<1>(g_wuT); }

// ---------------- GEMM2: A = g_hh fp16, B = g_wdT fp16, atomic epilogue --------
__global__ __launch_bounds__(256) void k_gemm2_mma(float* __restrict__ out) {
    extern __shared__ __half smh[];
    int total = g_offpad[NEXP];
    int mbase = blockIdx.y * BM;
    if (mbase >= total) return;
    int e = 0;
#pragma unroll
    for (int i = 0; i < NEXP; i++) if (mbase >= g_offpad[i + 1]) e = i + 1;

    const __half* W = g_wdT + (size_t)e * DIM * HID;   // [n=DIM][k=HID]
    int ncol = blockIdx.x * BN;

    int tid = threadIdx.x;
    uint32_t smb = smem_u32(smh);

    int row0 = tid >> 3, chk = (tid & 7) * 8;
    uint32_t adst[4], bdst[4];
    const __half *asrc[4], *bsrc[4];
#pragma unroll
    for (int p = 0; p < 4; p++) {
        int row = row0 + p * 32;
        adst[p] = (uint32_t)((row * SAH + chk) * 2);
        bdst[p] = (uint32_t)((ATILEH + row * SAH + chk) * 2);
        asrc[p] = g_hh + (size_t)(mbase + row) * HID + chk;
        bsrc[p] = W + (size_t)(ncol + row) * HID + chk;
    }

    int lane = tid & 31, gid = lane >> 2, tig = lane & 3;
    int wm = (tid >> 5) & 3, wn = tid >> 7;
    uint32_t aln = (uint32_t)(((wm * 32 + (lane & 15)) * SAH + (lane >> 4) * 8) * 2);
    uint32_t bln = (uint32_t)((ATILEH +
        (wn * 64 + (lane & 7) + ((lane >> 4) << 3)) * SAH +
        ((lane >> 3) & 1) * 8) * 2);

    float acc[2][8][4];
#pragma unroll
    for (int mt = 0; mt < 2; mt++)
#pragma unroll
        for (int nt = 0; nt < 8; nt++)
#pragma unroll
            for (int q = 0; q < 4; q++) acc[mt][nt][q] = 0.f;

    const int NT = HID / BK;            // 64
#pragma unroll
    for (int t = 0; t < 2; t++) {
        uint32_t base = smb + t * STGB;
        int k0 = t * BK;
#pragma unroll
        for (int p = 0; p < 4; p++) cp16h(base + adst[p], asrc[p] + k0, 16);
#pragma unroll
        for (int p = 0; p < 4; p++) cp16h(base + bdst[p], bsrc[p] + k0, 16);
        CP_COMMIT();
    }

    for (int i = 0; i < NT; i++) {
        CP_WAIT1();
        __syncthreads();
        int t = i + 2;
        if (t < NT) {
            uint32_t base = smb + (t % NSTG) * STGB;
            int k0 = t * BK;
#pragma unroll
            for (int p = 0; p < 4; p++) cp16h(base + adst[p], asrc[p] + k0, 16);
#pragma unroll
            for (int p = 0; p < 4; p++) cp16h(base + bdst[p], bsrc[p] + k0, 16);
        }
        CP_COMMIT();

        uint32_t stg = smb + (uint32_t)(i % NSTG) * STGB;
#pragma unroll
        for (int ks = 0; ks < 4; ks++) {
            uint32_t a[2][4], b[4][4];
#pragma unroll
            for (int mt = 0; mt < 2; mt++)
                ldsm_x4(a[mt], stg + aln + (uint32_t)(mt * 16 * SAH * 2 + ks * 32));
#pragma unroll
            for (int j = 0; j < 4; j++)
                ldsm_x4(b[j], stg + bln + (uint32_t)(j * 16 * SAH * 2 + ks * 32));
#pragma unroll
            for (int mt = 0; mt < 2; mt++)
#pragma unroll
                for (int j = 0; j < 4; j++) {
                    mma_f16(acc[mt][2 * j],     a[mt], &b[j][0]);
                    mma_f16(acc[mt][2 * j + 1], a[mt], &b[j][2]);
                }
        }
    }

#pragma unroll
    for (int mt = 0; mt < 2; mt++) {
        int slot = mbase + wm * 32 + mt * 16 + gid;
        int tok0 = g_perm[slot],     tok1 = g_perm[slot + 8];
        float w0 = g_permw[slot],    w1 = g_permw[slot + 8];
#pragma unroll
        for (int nt = 0; nt < 8; nt++) {
            int c = ncol + wn * 64 + nt * 8 + 2 * tig;
            if (tok0 >= 0) {
                float* op = out + (size_t)tok0 * DIM + c;
                atomicAdd(op,     w0 * acc[mt][nt][0]);
                atomicAdd(op + 1, w0 * acc[mt][nt][1]);
            }
            if (tok1 >= 0) {
                float* op = out + (size_t)tok1 * DIM + c;
                atomicAdd(op,     w1 * acc[mt][nt][2]);
                atomicAdd(op + 1, w1 * acc[mt][nt][3]);
            }
        }
    }
}

// ---------------- launch: fork-join streams to overlap transposes ----------------
extern "C" void kernel_launch(void* const* d_in, const int* in_sizes, int n_in,
                              void* d_out, int out_size) {
    const float* x      = (const float*)d_in[0];
    const float* gate_w = (const float*)d_in[1];
    const float* w_gate = (const float*)d_in[2];
    const float* w_up   = (const float*)d_in[3];
    const float* w_down = (const float*)d_in[4];
    float* out = (float*)d_out;

    static bool inited = false;
    static cudaStream_t s1, s2;
    static cudaEvent_t eF, eWg, eWu, eWd, eZ;
    if (!inited) {
        cudaFuncSetAttribute(k_g1gate, cudaFuncAttributeMaxDynamicSharedMemorySize,
                             SMEM_DYN);
        cudaFuncSetAttribute(k_g1up, cudaFuncAttributeMaxDynamicSharedMemorySize,
                             SMEM_DYN);
        cudaFuncSetAttribute(k_gemm2_mma, cudaFuncAttributeMaxDynamicSharedMemorySize,
                             SMEM_DYN);
        cudaStreamCreateWithFlags(&s1, cudaStreamNonBlocking);
        cudaStreamCreateWithFlags(&s2, cudaStreamNonBlocking);
        cudaEventCreateWithFlags(&eF,  cudaEventDisableTiming);
        cudaEventCreateWithFlags(&eWg, cudaEventDisableTiming);
        cudaEventCreateWithFlags(&eWu, cudaEventDisableTiming);
        cudaEventCreateWithFlags(&eWd, cudaEventDisableTiming);
        cudaEventCreateWithFlags(&eZ,  cudaEventDisableTiming);
        inited = true;
    }

    // fork
    cudaEventRecord(eF, 0);
    cudaStreamWaitEvent(s1, eF, 0);
    cudaStreamWaitEvent(s2, eF, 0);

    // s1: weight transposes (independent of routing chain)
    dim3 trb(32, 8);
    k_tr<<<dim3(HID / 64, DIM / 64, NEXP), trb, 0, s1>>>(w_gate, DIM, HID, 0);
    cudaEventRecord(eWg, s1);
    k_tr<<<dim3(HID / 64, DIM / 64, NEXP), trb, 0, s1>>>(w_up,   DIM, HID, 1);
    cudaEventRecord(eWu, s1);
    k_tr<<<dim3(DIM / 64, HID / 64, NEXP), trb, 0, s1>>>(w_down, HID, DIM, 2);
    cudaEventRecord(eWd, s1);

    // s2: output zeroing (needed only by gemm2)
    k_zero_out<<<2048, 256, 0, s2>>>((float4*)out, (T_TOK * DIM) / 4);
    cudaEventRecord(eZ, s2);

    // main: routing chain
    k_init<<<MAXPAD / 256, 256>>>();
    k_gate<<<T_TOK / 8, 256>>>(x, gate_w);
    k_offsets<<<1, 32>>>(out);
    k_scatter<<<(2 * T_TOK) / 256, 256>>>();

    // join + GEMMs
    cudaStreamWaitEvent(0, eWg, 0);
    k_g1gate<<<dim3(HID / BN, NMPAD), 256, SMEM_DYN>>>();
    cudaStreamWaitEvent(0, eWu, 0);
    k_g1up<<<dim3(HID / BN, NMPAD), 256, SMEM_DYN>>>();
    cudaStreamWaitEvent(0, eWd, 0);
    cudaStreamWaitEvent(0, eZ, 0);
    k_gemm2_mma<<<dim3(DIM / BN, NMPAD), 256, SMEM_DYN>>>(out);
}